// round 17
// baseline (speedup 1.0000x reference)
#include <cuda_runtime.h>
#include <cuda_fp16.h>
#include <math.h>
#include <stdint.h>

// ---------------- problem constants ----------------
#define S_LEN   2048
#define BATCH   2
#define T_TOK   (BATCH * S_LEN)
#define HIDDEN  2048
#define QLORA   1536
#define KVLORA  512
#define NHEADS  16
#define NOPE    128
#define ROPE_D  64
#define QHD     192
#define VHD     128
#define KVW     576

// ---------------- scratch ----------------
__device__ float g_qa [T_TOK * QLORA];
__device__ float g_ckv[T_TOK * KVW];

__device__ __half g_X16[T_TOK * HIDDEN];
__device__ __half g_wqa16[QLORA * HIDDEN];
__device__ __half g_wqb16[NHEADS*QHD*QLORA];
__device__ __half g_wkva16[KVW * HIDDEN];
__device__ __half g_wkvb16[NHEADS*256*KVLORA];
__device__ __half g_wo16[HIDDEN*NHEADS*VHD];
__device__ __half g_qan16[T_TOK * QLORA];
__device__ __half g_ckvn16[T_TOK * KVLORA];
__device__ __half g_q16[T_TOK * NHEADS * QHD];
__device__ __half g_kv16[T_TOK * NHEADS * 256];
__device__ __half g_kpe16[T_TOK * ROPE_D];
__device__ __half g_ctx16[T_TOK * NHEADS*VHD];

// ---------------- common helpers ----------------
__device__ __forceinline__ uint32_t smem_u32(const void* p) {
    uint32_t a;
    asm("{ .reg .u64 t; cvta.to.shared.u64 t, %1; cvt.u32.u64 %0, t; }" : "=r"(a) : "l"(p));
    return a;
}
__device__ __forceinline__ void ldm4(uint32_t* r, uint32_t addr) {
    asm volatile("ldmatrix.sync.aligned.m8n8.x4.shared.b16 {%0,%1,%2,%3}, [%4];"
                 : "=r"(r[0]), "=r"(r[1]), "=r"(r[2]), "=r"(r[3]) : "r"(addr));
}
__device__ __forceinline__ void ldm4t(uint32_t* r, uint32_t addr) {
    asm volatile("ldmatrix.sync.aligned.m8n8.x4.trans.shared.b16 {%0,%1,%2,%3}, [%4];"
                 : "=r"(r[0]), "=r"(r[1]), "=r"(r[2]), "=r"(r[3]) : "r"(addr));
}
__device__ __forceinline__ void mma16816h(float* d, const uint32_t* a, const uint32_t* b) {
    asm volatile("mma.sync.aligned.m16n8k16.row.col.f32.f16.f16.f32 "
                 "{%0,%1,%2,%3}, {%4,%5,%6,%7}, {%8,%9}, {%0,%1,%2,%3};"
                 : "+f"(d[0]), "+f"(d[1]), "+f"(d[2]), "+f"(d[3])
                 : "r"(a[0]), "r"(a[1]), "r"(a[2]), "r"(a[3]), "r"(b[0]), "r"(b[1]));
}
__device__ __forceinline__ void cpa16(uint32_t dst, const void* src, uint32_t sz) {
    asm volatile("cp.async.cg.shared.global [%0], [%1], 16, %2;"
                 :: "r"(dst), "l"(src), "r"(sz) : "memory");
}
__device__ __forceinline__ void split1h(float v, __half& h, __half& l) {
    h = __float2half_rn(v);
    l = __float2half_rn(v - __half2float(h));
}

// ---------------- merged convert fp32 -> fp16 single, 6 regions ----------------
struct Cvt6P {
    const float* x[6];
    __half* h[6];
    int off[7];
};
__global__ void cvt6_kernel(Cvt6P P) {
    int i = blockIdx.x * blockDim.x + threadIdx.x;
    if (i >= P.off[6]) return;
    int r = 0;
#pragma unroll
    for (int k = 1; k < 6; ++k) if (i >= P.off[k]) r = k;
    int j = i - P.off[r];
    float4 v = ((const float4*)P.x[r])[j];
    __half2 hp0 = __halves2half2(__float2half_rn(v.x), __float2half_rn(v.y));
    __half2 hp1 = __halves2half2(__float2half_rn(v.z), __float2half_rn(v.w));
    uint2 hh; hh.x = *(uint32_t*)&hp0; hh.y = *(uint32_t*)&hp1;
    ((uint2*)P.h[r])[j] = hh;
}

// ============================================================================
// fp16 GEMM: C = A * B^T. 128x128 CTA tile, 128 threads (4 warps, 64x64),
// 2 CTAs/SM. BK=64, 3-stage cp.async ring, one sync per chunk.
// ============================================================================
#define SMSTR 144                      // 64 fp16 = 128B + 16B pad
#define TILEB (128 * SMSTR)            // 18432
#define STAGEB (2 * TILEB)             // 36864 (A, B)
#define NSTAGE 3
#define GEMM_SMEM (NSTAGE * STAGEB)    // 110592

struct GemmP {
    const __half *A, *B;
    float* C;
    __half *Hh;
    int N, K;
};

__global__ __launch_bounds__(128, 2) void fp_gemm_dual(GemmP P0, GemmP P1, int xsplit) {
    extern __shared__ char sm[];
    const bool first = ((int)blockIdx.x < xsplit);
    const GemmP p = first ? P0 : P1;
    const int n0 = (first ? blockIdx.x : (blockIdx.x - xsplit)) * 128;
    const int K = p.K, N = p.N;

    const int tid = threadIdx.x;
    const int wid = tid >> 5;
    const int lane = tid & 31;
    const int m0 = blockIdx.y * 128;
    const int nvalid = (N - n0 < 128) ? (N - n0) : 128;

    const uint32_t sbase = smem_u32(sm);
    const int wr = wid >> 1, wc = wid & 1;               // 2x2 warps, 64x64 each
    const uint32_t a_row = wr * 64 + (lane & 15);
    const uint32_t a_colb = (lane >> 4) * 16;
    const uint32_t b_row = wc * 64 + (lane & 7) + ((lane >> 4) << 3);
    const uint32_t b_colb = ((lane >> 3) & 1) * 16;

    float acc[4][8][4];
#pragma unroll
    for (int i = 0; i < 4; ++i)
#pragma unroll
        for (int j = 0; j < 8; ++j)
#pragma unroll
            for (int e = 0; e < 4; ++e) acc[i][j][e] = 0.f;

    const int nch = K >> 6;

    // copy: 2048 x 16B units per chunk, 16 per thread
    auto issue_chunk = [&](int c, int st) {
        const int k0 = c << 6;
        const uint32_t stb = sbase + st * STAGEB;
#pragma unroll
        for (int i = 0; i < 16; ++i) {
            int u = tid + i * 128;
            int tile = u >> 10;             // 0=A 1=B
            int row = (u & 1023) >> 3;
            int c16 = u & 7;
            uint32_t dst = stb + tile * TILEB + row * SMSTR + c16 * 16;
            const __half* src;
            uint32_t sz = 16;
            if (tile == 0) src = p.A + (size_t)(m0 + row) * K + k0 + c16 * 8;
            else {
                src = p.B + (size_t)(n0 + row) * K + k0 + c16 * 8;
                if (row >= nvalid) sz = 0;
            }
            cpa16(dst, src, sz);
        }
        asm volatile("cp.async.commit_group;" ::: "memory");
    };

    issue_chunk(0, 0);
    if (nch > 1) issue_chunk(1, 1); else asm volatile("cp.async.commit_group;" ::: "memory");

    int st = 0, nst = 2;   // stage of c; stage of c+2
    for (int c = 0; c < nch; ++c) {
        asm volatile("cp.async.wait_group 1;" ::: "memory");
        __syncthreads();
        if (c + 2 < nch) issue_chunk(c + 2, nst);
        else asm volatile("cp.async.commit_group;" ::: "memory");

        const uint32_t stb = sbase + st * STAGEB;
        st = (st + 1 == NSTAGE) ? 0 : st + 1;
        nst = (nst + 1 == NSTAGE) ? 0 : nst + 1;

#pragma unroll
        for (int ks = 0; ks < 4; ++ks) {
            const uint32_t kb = ks * 32;
            uint32_t ah[4][4], bh[4][4];
#pragma unroll
            for (int i = 0; i < 4; ++i)
                ldm4(ah[i], stb + (a_row + i * 16) * SMSTR + a_colb + kb);
#pragma unroll
            for (int jp = 0; jp < 4; ++jp)
                ldm4(bh[jp], stb + TILEB + (b_row + jp * 16) * SMSTR + b_colb + kb);
#pragma unroll
            for (int i = 0; i < 4; ++i)
#pragma unroll
                for (int j = 0; j < 8; ++j)
                    mma16816h(acc[i][j], ah[i], &bh[j >> 1][(j & 1) * 2]);
        }
    }

    const int gid = lane >> 2, tig = lane & 3;
#pragma unroll
    for (int i = 0; i < 4; ++i) {
#pragma unroll
        for (int rr = 0; rr < 2; ++rr) {
            int row = m0 + wr * 64 + i * 16 + gid + rr * 8;
#pragma unroll
            for (int j = 0; j < 8; ++j) {
                int col = n0 + wc * 64 + j * 8 + tig * 2;
                if (col < N) {
                    float v0 = acc[i][j][rr * 2], v1 = acc[i][j][rr * 2 + 1];
                    if (p.C) *(float2*)(p.C + (size_t)row * N + col) = make_float2(v0, v1);
                    if (p.Hh) {
                        __half2 hp = __halves2half2(__float2half_rn(v0), __float2half_rn(v1));
                        *(uint32_t*)(p.Hh + (size_t)row * N + col) = *(uint32_t*)&hp;
                    }
                }
            }
        }
    }
}

// ---------------- YaRN ----------------
__device__ __forceinline__ void yarn_cs(int pos, int j, float& c, float& s) {
    float ex   = __expf(-(float)(2 * j) * (9.210340371976184f / 64.f));
    float fi   = ex * 0.025f;
    float ramp = ((float)j - 10.f) * (1.f / 13.f);
    ramp = fminf(fmaxf(ramp, 0.f), 1.f);
    float invf = fi * ramp + ex * (1.f - ramp);
    float ang  = (float)pos * invf;
    c = cosf(ang); s = sinf(ang);
}

// ---------------- dual RMSNorm -> fp16 single (+ fused rope_k on P1) --------
struct RmsP {
    const float* x; const float* w;
    __half *y;
    int D, in_stride;
};
__global__ void rmsnorm_dual(RmsP P0, RmsP P1, const int* __restrict__ pos_ids,
                             __half* __restrict__ kpe) {
    const bool second = (blockIdx.y == 1);
    const RmsP p = second ? P1 : P0;
    const int row = blockIdx.x;
    const float* xr = p.x + (size_t)row * p.in_stride;
    float ss = 0.f;
    for (int d = threadIdx.x; d < p.D; d += blockDim.x) { float v = xr[d]; ss += v * v; }
    __shared__ float red[32];
#pragma unroll
    for (int o = 16; o; o >>= 1) ss += __shfl_xor_sync(0xffffffffu, ss, o);
    if ((threadIdx.x & 31) == 0) red[threadIdx.x >> 5] = ss;
    __syncthreads();
    if (threadIdx.x < 32) {
        float v = (threadIdx.x < (blockDim.x >> 5)) ? red[threadIdx.x] : 0.f;
#pragma unroll
        for (int o = 16; o; o >>= 1) v += __shfl_xor_sync(0xffffffffu, v, o);
        if (threadIdx.x == 0) red[0] = v;
    }
    __syncthreads();
    float scale = rsqrtf(red[0] / (float)p.D + 1e-6f);
    for (int d = threadIdx.x; d < p.D; d += blockDim.x) {
        float v = p.w[d] * xr[d] * scale;
        p.y[(size_t)row * p.D + d] = __float2half_rn(v);
    }
    // fused rope_k (P1 rows only; threads 0..31)
    if (second && threadIdx.x < 32) {
        const int j = threadIdx.x;
        const int pos = pos_ids[row];
        float c, s; yarn_cs(pos, j, c, s);
        float x0 = xr[KVLORA + 2 * j], x1 = xr[KVLORA + 2 * j + 1];
        kpe[row * ROPE_D + j]      = __float2half_rn(x0 * c - x1 * s);
        kpe[row * ROPE_D + 32 + j] = __float2half_rn(x1 * c + x0 * s);
    }
}

__global__ void rope_q_kernel(__half* __restrict__ q, const int* __restrict__ pos_ids) {
    const int t = blockIdx.x >> 4;
    const int h = blockIdx.x & 15;
    const int j = threadIdx.x;
    const int pos = pos_ids[t];
    __half* x = q + (size_t)t * (NHEADS * QHD) + h * QHD + NOPE;
    float c, s; yarn_cs(pos, j, c, s);
    float x0 = __half2float(x[2*j]);
    float x1 = __half2float(x[2*j+1]);
    float r0 = x0 * c - x1 * s, r1 = x1 * c + x0 * s;
    __syncwarp();
    x[j]      = __float2half_rn(r0);
    x[32 + j] = __float2half_rn(r1);
}

// ============================================================================
// Flash attention, fp16 HMMA. BM=64, BN=64, 4 warps, 2 CTAs/SM.
// Q single (1-term QK), P 2-term AV, P in registers. exp2-domain softmax.
// ============================================================================
#define FL_KSTR 400
#define FL_VSTR 272
#define FL_KVSTG (64 * FL_KSTR + 64 * FL_VSTR)
#define FL_VOFF  (64 * FL_KSTR)
#define FL_QSTR 400
#define FL_SMEM (2 * FL_KVSTG)

__global__ __launch_bounds__(128, 2) void flash_mma(
    const __half* __restrict__ q,
    const __half* __restrict__ kv,
    const __half* __restrict__ kpe,
    __half* __restrict__ ctx)
{
    extern __shared__ char sm[];
    const uint32_t sb = smem_u32(sm);
    const int qt = (int)gridDim.x - 1 - (int)blockIdx.x;
    const int hh = blockIdx.y, b = blockIdx.z;
    const int tid = threadIdx.x, wid = tid >> 5, lane = tid & 31;
    const int gid = lane >> 2, tig = lane & 3;
    const int t0 = b * S_LEN;

    const uint32_t a_row = wid * 16 + (lane & 15);
    const uint32_t a_colb = (lane >> 4) * 16;
    const uint32_t k_roff = (lane & 7) + ((lane >> 4) << 3);
    const uint32_t k_colb = ((lane >> 3) & 1) * 16;
    const uint32_t v_koff = (lane & 7) + ((lane >> 3) & 1) * 8;
    const uint32_t v_noff = (lane >> 4) * 8;

    for (int idx = tid; idx < 64 * 24; idx += 128) {
        int r = idx / 24, u = idx % 24;
        size_t g = (size_t)(t0 + qt * 64 + r) * (NHEADS * QHD) + hh * QHD + u * 8;
        *(uint4*)(sm + r * FL_QSTR + u * 16) = *(const uint4*)(q + g);
    }
    __syncthreads();
    uint32_t qf[12][4];
#pragma unroll
    for (int ks = 0; ks < 12; ++ks)
        ldm4(qf[ks], sb + a_row * FL_QSTR + a_colb + ks * 32);
    __syncthreads();

    auto issue_kv = [&](int kt) {
        const uint32_t stb = sb + (kt & 1) * FL_KVSTG;
        for (int idx = tid; idx < 64 * 24; idx += 128) {
            int r = idx / 24, u = idx % 24;
            int t = t0 + kt * 64 + r;
            const __half* src;
            if (u < 16) src = kv + (size_t)t * (NHEADS * 256) + hh * 256 + u * 8;
            else        src = kpe + (size_t)t * ROPE_D + (u - 16) * 8;
            cpa16(stb + r * FL_KSTR + u * 16, src, 16);
        }
        for (int idx = tid; idx < 64 * 16; idx += 128) {
            int r = idx >> 4, u = idx & 15;
            size_t g = (size_t)(t0 + kt * 64 + r) * (NHEADS * 256) + hh * 256 + 128 + u * 8;
            cpa16(stb + FL_VOFF + r * FL_VSTR + u * 16, kv + g, 16);
        }
        asm volatile("cp.async.commit_group;" ::: "memory");
    };

    float m_i[2], l_i[2], O[16][4];
    m_i[0] = m_i[1] = -1e30f; l_i[0] = l_i[1] = 0.f;
#pragma unroll
    for (int nf = 0; nf < 16; ++nf)
#pragma unroll
        for (int e = 0; e < 4; ++e) O[nf][e] = 0.f;

    const float mm = 0.1f * logf(40.f) + 1.f;
    // exp2-domain scale: sc2 = softmax_scale * log2(e)
    const float sc2 = mm * mm * rsqrtf(192.f) * 1.4426950408889634f;

    const int nkt = qt + 1;
    issue_kv(0);

    for (int kt = 0; kt < nkt; ++kt) {
        if (kt + 1 < nkt) {
            issue_kv(kt + 1);
            asm volatile("cp.async.wait_group 1;" ::: "memory");
        } else {
            asm volatile("cp.async.wait_group 0;" ::: "memory");
        }
        __syncthreads();
        const uint32_t stb = sb + (kt & 1) * FL_KVSTG;

        // ---- QK ----
        float s[8][4];
#pragma unroll
        for (int nf = 0; nf < 8; ++nf)
#pragma unroll
            for (int e = 0; e < 4; ++e) s[nf][e] = 0.f;

#pragma unroll
        for (int ks = 0; ks < 12; ++ks) {
#pragma unroll
            for (int jb = 0; jb < 4; ++jb) {
                uint32_t bh4[4];
                uint32_t brow = jb * 16 + k_roff;
                ldm4(bh4, stb + brow * FL_KSTR + k_colb + ks * 32);
                mma16816h(s[2*jb],   qf[ks], &bh4[0]);
                mma16816h(s[2*jb+1], qf[ks], &bh4[2]);
            }
        }

        // ---- softmax (log2 domain) ----
#pragma unroll
        for (int rr = 0; rr < 2; ++rr) {
            int grow = qt * 64 + wid * 16 + gid + rr * 8;
            float tmax = -1e30f;
#pragma unroll
            for (int nf = 0; nf < 8; ++nf) {
#pragma unroll
                for (int e = 0; e < 2; ++e) {
                    int gcol = kt * 64 + nf * 8 + tig * 2 + e;
                    float v = s[nf][rr * 2 + e] * sc2;
                    if (gcol > grow) v = -1e30f;
                    s[nf][rr * 2 + e] = v;
                    tmax = fmaxf(tmax, v);
                }
            }
            tmax = fmaxf(tmax, __shfl_xor_sync(0xffffffffu, tmax, 1));
            tmax = fmaxf(tmax, __shfl_xor_sync(0xffffffffu, tmax, 2));
            float nm = fmaxf(m_i[rr], tmax);
            float fac = exp2f(m_i[rr] - nm);
            float psum = 0.f;
#pragma unroll
            for (int nf = 0; nf < 8; ++nf) {
#pragma unroll
                for (int e = 0; e < 2; ++e) {
                    float pv = exp2f(s[nf][rr * 2 + e] - nm);
                    s[nf][rr * 2 + e] = pv;
                    psum += pv;
                }
            }
            psum += __shfl_xor_sync(0xffffffffu, psum, 1);
            psum += __shfl_xor_sync(0xffffffffu, psum, 2);
            l_i[rr] = l_i[rr] * fac + psum;
            m_i[rr] = nm;
#pragma unroll
            for (int nf = 0; nf < 16; ++nf) {
                O[nf][rr * 2] *= fac;
                O[nf][rr * 2 + 1] *= fac;
            }
        }

        // ---- P -> A-operand fragments (hi/lo) ----
        uint32_t aph[4][4], apl[4][4];
#pragma unroll
        for (int ks = 0; ks < 4; ++ks) {
#pragma unroll
            for (int q2 = 0; q2 < 2; ++q2) {
                int nf = 2 * ks + q2;
                __half h0,l0,h1,l1,h2,l2,h3,l3;
                split1h(s[nf][0], h0, l0); split1h(s[nf][1], h1, l1);
                split1h(s[nf][2], h2, l2); split1h(s[nf][3], h3, l3);
                __half2 ph01 = __halves2half2(h0, h1);
                __half2 ph23 = __halves2half2(h2, h3);
                __half2 pl01 = __halves2half2(l0, l1);
                __half2 pl23 = __halves2half2(l2, l3);
                aph[ks][2*q2]   = *(uint32_t*)&ph01;
                aph[ks][2*q2+1] = *(uint32_t*)&ph23;
                apl[ks][2*q2]   = *(uint32_t*)&pl01;
                apl[ks][2*q2+1] = *(uint32_t*)&pl23;
            }
        }

        // ---- AV ----
#pragma unroll
        for (int ks = 0; ks < 4; ++ks) {
            uint32_t vrow = ks * 16 + v_koff;
#pragma unroll
            for (int nb = 0; nb < 8; ++nb) {
                uint32_t bvh[4];
                uint32_t vcol = (nb * 16 + v_noff) * 2;
                ldm4t(bvh, stb + FL_VOFF + vrow * FL_VSTR + vcol);
                mma16816h(O[2*nb],   aph[ks], &bvh[0]);
                mma16816h(O[2*nb+1], aph[ks], &bvh[2]);
                mma16816h(O[2*nb],   apl[ks], &bvh[0]);
                mma16816h(O[2*nb+1], apl[ks], &bvh[2]);
            }
        }
        __syncthreads();
    }

#pragma unroll
    for (int rr = 0; rr < 2; ++rr) {
        float inv = 1.f / l_i[rr];
        int row = t0 + qt * 64 + wid * 16 + gid + rr * 8;
#pragma unroll
        for (int nf = 0; nf < 16; ++nf) {
            int col = nf * 8 + tig * 2;
            float v0 = O[nf][rr * 2] * inv, v1 = O[nf][rr * 2 + 1] * inv;
            __half2 hp = __halves2half2(__float2half_rn(v0), __float2half_rn(v1));
            size_t g = (size_t)row * (NHEADS * VHD) + hh * VHD + col;
            *(uint32_t*)(ctx + g) = *(uint32_t*)&hp;
        }
    }
}

// ---------------- launch ----------------
extern "C" void kernel_launch(void* const* d_in, const int* in_sizes, int n_in,
                              void* d_out, int out_size) {
    (void)in_sizes; (void)n_in; (void)out_size;
    const float* X     = (const float*)d_in[0];
    const int*   pos   = (const int*)  d_in[1];
    const float* wq_a  = (const float*)d_in[2];
    const float* qln   = (const float*)d_in[3];
    const float* wq_b  = (const float*)d_in[4];
    const float* wkv_a = (const float*)d_in[5];
    const float* kvln  = (const float*)d_in[6];
    const float* wkv_b = (const float*)d_in[7];
    const float* wo    = (const float*)d_in[8];
    float* out = (float*)d_out;

    float *qa, *ckv;
    __half *X16,*wqa16,*wqb16,*wkva16,*wkvb16,*wo16;
    __half *qan16,*ckvn16,*q16,*kv16,*kpe16,*ctx16;
    cudaGetSymbolAddress((void**)&qa, g_qa);
    cudaGetSymbolAddress((void**)&ckv, g_ckv);
    cudaGetSymbolAddress((void**)&X16, g_X16);
    cudaGetSymbolAddress((void**)&wqa16, g_wqa16);
    cudaGetSymbolAddress((void**)&wqb16, g_wqb16);
    cudaGetSymbolAddress((void**)&wkva16, g_wkva16);
    cudaGetSymbolAddress((void**)&wkvb16, g_wkvb16);
    cudaGetSymbolAddress((void**)&wo16, g_wo16);
    cudaGetSymbolAddress((void**)&qan16, g_qan16);
    cudaGetSymbolAddress((void**)&ckvn16, g_ckvn16);
    cudaGetSymbolAddress((void**)&q16, g_q16);
    cudaGetSymbolAddress((void**)&kv16, g_kv16);
    cudaGetSymbolAddress((void**)&kpe16, g_kpe16);
    cudaGetSymbolAddress((void**)&ctx16, g_ctx16);

    cudaFuncSetAttribute(fp_gemm_dual, cudaFuncAttributeMaxDynamicSharedMemorySize, GEMM_SMEM);
    cudaFuncSetAttribute(flash_mma, cudaFuncAttributeMaxDynamicSharedMemorySize, FL_SMEM);

    const dim3 blk(128);
    const int mt = T_TOK / 128;  // 32

    // merged input conversions (all single fp16)
    {
        Cvt6P P;
        P.x[0]=X;     P.h[0]=X16;
        P.x[1]=wq_a;  P.h[1]=wqa16;
        P.x[2]=wq_b;  P.h[2]=wqb16;
        P.x[3]=wkv_a; P.h[3]=wkva16;
        P.x[4]=wkv_b; P.h[4]=wkvb16;
        P.x[5]=wo;    P.h[5]=wo16;
        int lens[6] = { T_TOK*HIDDEN/4, QLORA*HIDDEN/4, NHEADS*QHD*QLORA/4,
                        KVW*HIDDEN/4, NHEADS*256*KVLORA/4, HIDDEN*NHEADS*VHD/4 };
        P.off[0] = 0;
        for (int i = 0; i < 6; ++i) P.off[i+1] = P.off[i] + lens[i];
        cvt6_kernel<<<(P.off[6] + 255) / 256, 256>>>(P);
    }

    // fused a-projections -> fp32
    {
        GemmP p0 = { X16, wqa16,  qa,  nullptr, QLORA, HIDDEN };
        GemmP p1 = { X16, wkva16, ckv, nullptr, KVW,   HIDDEN };
        fp_gemm_dual<<<dim3(QLORA/128 + (KVW+127)/128, mt), blk, GEMM_SMEM>>>(p0, p1, QLORA/128);
    }

    // fused rmsnorms -> fp16 (+ rope_k fused on the kv branch)
    {
        RmsP p0 = { qa, qln, qan16, QLORA, QLORA };
        RmsP p1 = { ckv, kvln, ckvn16, KVLORA, KVW };
        rmsnorm_dual<<<dim3(T_TOK, 2), 256>>>(p0, p1, pos, kpe16);
    }

    // fused b-projections: q -> fp16 single ; kv -> fp16 single
    {
        GemmP p0 = { qan16,  wqb16,  nullptr, q16,  NHEADS*QHD, QLORA };
        GemmP p1 = { ckvn16, wkvb16, nullptr, kv16, NHEADS*256, KVLORA };
        fp_gemm_dual<<<dim3((NHEADS*QHD)/128 + (NHEADS*256)/128, mt), blk, GEMM_SMEM>>>(
            p0, p1, (NHEADS*QHD)/128);
    }

    rope_q_kernel<<<T_TOK * NHEADS, 32>>>(q16, pos);

    flash_mma<<<dim3(S_LEN / 64, NHEADS, BATCH), dim3(128), FL_SMEM>>>(q16, kv16, kpe16, ctx16);

    // output projection -> fp32 out
    {
        GemmP p0 = { ctx16, wo16, out, nullptr, HIDDEN, NHEADS*VHD };
        fp_gemm_dual<<<dim3(HIDDEN/128, mt), blk, GEMM_SMEM>>>(p0, p0, HIDDEN/128);
    }
}